// round 2
// baseline (speedup 1.0000x reference)
#include <cuda_runtime.h>
#include <cuda_bf16.h>
#include <stdint.h>

#define DD 128
#define NMAX 100000

// Scratch (allowed: __device__ globals, no runtime allocation)
__device__ float g_agg[(size_t)NMAX * DD];
__device__ float g_h0 [(size_t)NMAX * DD];
__device__ float g_h1 [(size_t)NMAX * DD];
__device__ float g_deg[NMAX];

// -------------------- degree --------------------
__global__ void deg_kernel(const int* __restrict__ dst, float* __restrict__ deg, long long E) {
    long long e = (long long)blockIdx.x * blockDim.x + threadIdx.x;
    if (e < E) {
        int d = dst[e];
        atomicAdd(&deg[d], 1.0f);
    }
}

__global__ void invdeg_kernel(float* __restrict__ deg, int n) {
    int i = blockIdx.x * blockDim.x + threadIdx.x;
    if (i < n) deg[i] = 1.0f / fmaxf(deg[i], 1.0f);
}

// -------------------- scatter (mean-agg numerator) --------------------
__device__ __forceinline__ void red_add_v4(float* p, float4 v) {
    asm volatile("red.global.add.v4.f32 [%0], {%1, %2, %3, %4};"
                 :: "l"(p), "f"(v.x), "f"(v.y), "f"(v.z), "f"(v.w) : "memory");
}

// One warp per edge; each lane moves one float4 (32 lanes * 16B = 512B row).
__global__ void scatter_kernel(const float* __restrict__ h,
                               const int* __restrict__ ei,  // [2*E], src then dst (int32)
                               float* __restrict__ agg, long long E) {
    long long idx = (long long)blockIdx.x * blockDim.x + threadIdx.x;
    long long e = idx >> 5;
    int lane = (int)(idx & 31);
    if (e >= E) return;
    int s = __ldg(&ei[e]);
    int d = __ldg(&ei[E + e]);
    const float4* hv = (const float4*)(h + (long long)s * DD);
    float4 v = __ldg(&hv[lane]);
    red_add_v4(agg + (long long)d * DD + (long long)lane * 4, v);
}

// -------------------- fused SAGE GEMM --------------------
// out[n, :] = (agg[n,:]*invdeg[n]) @ Wl^T + h[n,:] @ Wr^T + b   (+ optional ReLU)
// Treated as C = A @ Wt with A = [mean | h] (N x 256), Wt = [Wl^T ; Wr^T] (256 x 128).
// Per block: 64 rows x 128 cols; full Wt (128KB) + A tile transposed (64KB) in smem.
#define GEMM_SMEM ((256 * 128 + 256 * 64) * sizeof(float))

__global__ void __launch_bounds__(256, 1)
sage_gemm(const float* __restrict__ agg, const float* __restrict__ h,
          const float* __restrict__ invdeg,
          const float* __restrict__ Wl, const float* __restrict__ Wr,
          const float* __restrict__ bias, float* __restrict__ out,
          int n, int relu) {
    extern __shared__ float sm[];
    float* Wt = sm;                 // [256][128] : Wt[k][j]
    float* As = sm + 256 * 128;     // [256][64]  : As[k][r]

    int tid = threadIdx.x;
    int row0 = blockIdx.x * 64;

    // Load W transposed into smem: Wt[k][j] = (k<128 ? Wl[j][k] : Wr[j][k-128])
    #pragma unroll
    for (int i = 0; i < 32; i++) {
        int fidx = i * 256 + tid;          // 0..8191
        int j  = fidx % 128;
        int kc = fidx / 128;               // 0..63
        int k  = kc * 4;
        float4 v;
        if (k < 128) v = __ldg((const float4*)(Wl + j * DD + k));
        else         v = __ldg((const float4*)(Wr + j * DD + (k - 128)));
        Wt[(k + 0) * 128 + j] = v.x;
        Wt[(k + 1) * 128 + j] = v.y;
        Wt[(k + 2) * 128 + j] = v.z;
        Wt[(k + 3) * 128 + j] = v.w;
    }

    // Load A tile transposed: As[k][r] ; mean scaling folded in.
    #pragma unroll
    for (int i = 0; i < 16; i++) {
        int fidx = i * 256 + tid;          // 0..4095 float4
        int r  = fidx % 64;
        int kc = fidx / 64;                // 0..63
        int k  = kc * 4;
        int row = row0 + r;
        float4 v = make_float4(0.f, 0.f, 0.f, 0.f);
        if (row < n) {
            if (k < 128) {
                v = __ldg((const float4*)(agg + (long long)row * DD + k));
                float sc = __ldg(&invdeg[row]);
                v.x *= sc; v.y *= sc; v.z *= sc; v.w *= sc;
            } else {
                v = __ldg((const float4*)(h + (long long)row * DD + (k - 128)));
            }
        }
        As[(k + 0) * 64 + r] = v.x;
        As[(k + 1) * 64 + r] = v.y;
        As[(k + 2) * 64 + r] = v.z;
        As[(k + 3) * 64 + r] = v.w;
    }
    __syncthreads();

    int tx = tid & 31;        // column group: cols tx*4 .. tx*4+3
    int ty = tid >> 5;        // row group:    rows ty*8 .. ty*8+7
    int col = tx * 4;

    float acc[8][4];
    #pragma unroll
    for (int r = 0; r < 8; r++)
        #pragma unroll
        for (int c = 0; c < 4; c++) acc[r][c] = 0.f;

    #pragma unroll 4
    for (int k = 0; k < 256; k++) {
        float4 w  = *(const float4*)(Wt + k * 128 + col);
        float4 a0 = *(const float4*)(As + k * 64 + ty * 8);
        float4 a1 = *(const float4*)(As + k * 64 + ty * 8 + 4);
        float ar[8] = {a0.x, a0.y, a0.z, a0.w, a1.x, a1.y, a1.z, a1.w};
        #pragma unroll
        for (int r = 0; r < 8; r++) {
            acc[r][0] += ar[r] * w.x;
            acc[r][1] += ar[r] * w.y;
            acc[r][2] += ar[r] * w.z;
            acc[r][3] += ar[r] * w.w;
        }
    }

    float4 bv = __ldg((const float4*)(bias + col));
    #pragma unroll
    for (int r = 0; r < 8; r++) {
        int row = row0 + ty * 8 + r;
        if (row < n) {
            float4 o;
            o.x = acc[r][0] + bv.x;
            o.y = acc[r][1] + bv.y;
            o.z = acc[r][2] + bv.z;
            o.w = acc[r][3] + bv.w;
            if (relu) {
                o.x = fmaxf(o.x, 0.f); o.y = fmaxf(o.y, 0.f);
                o.z = fmaxf(o.z, 0.f); o.w = fmaxf(o.w, 0.f);
            }
            *(float4*)(out + (long long)row * DD + col) = o;
        }
    }
}

// -------------------- launch --------------------
extern "C" void kernel_launch(void* const* d_in, const int* in_sizes, int n_in,
                              void* d_out, int out_size) {
    const float* x   = (const float*)d_in[0];
    const int*   ei  = (const int*)d_in[1];     // int32 (JAX x64 disabled coerces int64->int32)
    const float* W1l = (const float*)d_in[2];
    const float* W1r = (const float*)d_in[3];
    const float* W2l = (const float*)d_in[4];
    const float* W2r = (const float*)d_in[5];
    const float* W3l = (const float*)d_in[6];
    const float* W3r = (const float*)d_in[7];
    const float* b1  = (const float*)d_in[8];
    const float* b2  = (const float*)d_in[9];
    const float* b3  = (const float*)d_in[10];
    float* out = (float*)d_out;

    int n = in_sizes[0] / DD;
    long long E = (long long)in_sizes[1] / 2;

    float *agg, *h0, *h1, *deg;
    cudaGetSymbolAddress((void**)&agg, g_agg);
    cudaGetSymbolAddress((void**)&h0,  g_h0);
    cudaGetSymbolAddress((void**)&h1,  g_h1);
    cudaGetSymbolAddress((void**)&deg, g_deg);

    cudaFuncSetAttribute(sage_gemm, cudaFuncAttributeMaxDynamicSharedMemorySize,
                         (int)GEMM_SMEM);

    // degree -> invdeg (edges constant across layers)
    cudaMemsetAsync(deg, 0, (size_t)n * sizeof(float));
    deg_kernel<<<(unsigned)((E + 255) / 256), 256>>>(ei + E, deg, E);
    invdeg_kernel<<<(n + 255) / 256, 256>>>(deg, n);

    long long scat_threads = E * 32;
    unsigned scat_blocks = (unsigned)((scat_threads + 255) / 256);
    int gemm_blocks = (n + 63) / 64;
    size_t agg_bytes = (size_t)n * DD * sizeof(float);

    // Layer 1
    cudaMemsetAsync(agg, 0, agg_bytes);
    scatter_kernel<<<scat_blocks, 256>>>(x, ei, agg, E);
    sage_gemm<<<gemm_blocks, 256, GEMM_SMEM>>>(agg, x, deg, W1l, W1r, b1, h0, n, 1);

    // Layer 2
    cudaMemsetAsync(agg, 0, agg_bytes);
    scatter_kernel<<<scat_blocks, 256>>>(h0, ei, agg, E);
    sage_gemm<<<gemm_blocks, 256, GEMM_SMEM>>>(agg, h0, deg, W2l, W2r, b2, h1, n, 1);

    // Layer 3
    cudaMemsetAsync(agg, 0, agg_bytes);
    scatter_kernel<<<scat_blocks, 256>>>(h1, ei, agg, E);
    sage_gemm<<<gemm_blocks, 256, GEMM_SMEM>>>(agg, h1, deg, W3l, W3r, b3, out, n, 0);
}

// round 3
// speedup vs baseline: 1.9183x; 1.9183x over previous
#include <cuda_runtime.h>
#include <cuda_bf16.h>
#include <stdint.h>

#define DD 128
#define NMAX 100000
#define EMAX 3200000
typedef unsigned long long u64;

// -------- device-global scratch (no runtime allocation allowed) --------
__device__ float g_agg[(size_t)NMAX * DD];
__device__ float g_h0 [(size_t)NMAX * DD];
__device__ float g_h1 [(size_t)NMAX * DD];
__device__ int   g_cnt [NMAX];
__device__ int   g_cur [NMAX];
__device__ int   g_incl[NMAX];
__device__ int   g_bsum[512];
__device__ int   g_rowptr[NMAX + 1];
__device__ int   g_csr [EMAX];

// ==================== CSR build ====================
__global__ void deg_kernel(const int* __restrict__ dst, int* __restrict__ cnt, long long E) {
    long long e = (long long)blockIdx.x * blockDim.x + threadIdx.x;
    if (e < E) atomicAdd(&cnt[dst[e]], 1);
}

#define SB 256
__global__ void scan1(const int* __restrict__ cnt, int* __restrict__ incl,
                      int* __restrict__ bsum, int n) {
    __shared__ int sm[SB];
    int i = blockIdx.x * SB + threadIdx.x;
    int v = (i < n) ? cnt[i] : 0;
    sm[threadIdx.x] = v;
    __syncthreads();
    for (int off = 1; off < SB; off <<= 1) {
        int t = (threadIdx.x >= off) ? sm[threadIdx.x - off] : 0;
        __syncthreads();
        sm[threadIdx.x] += t;
        __syncthreads();
    }
    if (i < n) incl[i] = sm[threadIdx.x];
    if (threadIdx.x == SB - 1) bsum[blockIdx.x] = sm[SB - 1];
}

__global__ void scan2(int* __restrict__ bsum, int nb) {  // exclusive scan, nb <= 512
    __shared__ int sm[512];
    int v = (threadIdx.x < nb) ? bsum[threadIdx.x] : 0;
    sm[threadIdx.x] = v;
    __syncthreads();
    for (int off = 1; off < 512; off <<= 1) {
        int t = (threadIdx.x >= off) ? sm[threadIdx.x - off] : 0;
        __syncthreads();
        sm[threadIdx.x] += t;
        __syncthreads();
    }
    if (threadIdx.x < nb) bsum[threadIdx.x] = sm[threadIdx.x] - v;
}

__global__ void scan3(const int* __restrict__ incl, const int* __restrict__ cnt,
                      const int* __restrict__ bsum, int* __restrict__ rowptr,
                      int n, int E) {
    int i = blockIdx.x * 256 + threadIdx.x;
    if (i < n) rowptr[i] = incl[i] - cnt[i] + bsum[i / SB];
    if (i == 0) rowptr[n] = E;
}

__global__ void place_kernel(const int* __restrict__ ei, const int* __restrict__ rowptr,
                             int* __restrict__ cur, int* __restrict__ csr, long long E) {
    long long e = (long long)blockIdx.x * blockDim.x + threadIdx.x;
    if (e < E) {
        int s = ei[e];
        int d = ei[E + e];
        int pos = rowptr[d] + atomicAdd(&cur[d], 1);
        csr[pos] = s;
    }
}

// ==================== mean aggregation (warp per dst node) ====================
__global__ void agg_kernel(const float* __restrict__ h, const int* __restrict__ rowptr,
                           const int* __restrict__ csr, float* __restrict__ agg, int n) {
    int d = blockIdx.x * (blockDim.x >> 5) + (threadIdx.x >> 5);
    int lane = threadIdx.x & 31;
    if (d >= n) return;
    int beg = __ldg(&rowptr[d]);
    int end = __ldg(&rowptr[d + 1]);
    float4 acc = make_float4(0.f, 0.f, 0.f, 0.f);
    for (int j = beg; j < end; j += 32) {
        int cnt = min(32, end - j);
        int s = (lane < cnt) ? __ldg(&csr[j + lane]) : 0;
        #pragma unroll 4
        for (int t = 0; t < cnt; t++) {
            int ss = __shfl_sync(0xffffffffu, s, t);
            float4 v = __ldg((const float4*)(h + (long long)ss * DD) + lane);
            acc.x += v.x; acc.y += v.y; acc.z += v.z; acc.w += v.w;
        }
    }
    float inv = 1.0f / fmaxf((float)(end - beg), 1.0f);
    acc.x *= inv; acc.y *= inv; acc.z *= inv; acc.w *= inv;
    *((float4*)(agg + (long long)d * DD) + lane) = acc;
}

// ==================== fused SAGE GEMM (f32x2 packed FFMA) ====================
// out[n,:] = mean[n,:] @ Wl^T + h[n,:] @ Wr^T + b   (+ optional ReLU)
// C = A @ Wt, A = [mean | h] (N x 256), Wt = [Wl^T ; Wr^T] (256 x 128).
#define GEMM_SMEM ((256 * 128 + 256 * 64) * sizeof(float))

__device__ __forceinline__ void fma2(u64& d, u64 a, u64 b) {
    asm("fma.rn.f32x2 %0, %1, %2, %0;" : "+l"(d) : "l"(a), "l"(b));
}
__device__ __forceinline__ u64 dup2(float x) {
    u64 r;
    asm("mov.b64 %0, {%1, %1};" : "=l"(r) : "r"(__float_as_uint(x)));
    return r;
}
__device__ __forceinline__ void unpk(float& lo, float& hi, u64 v) {
    unsigned a, b;
    asm("mov.b64 {%0, %1}, %2;" : "=r"(a), "=r"(b) : "l"(v));
    lo = __uint_as_float(a); hi = __uint_as_float(b);
}

__global__ void __launch_bounds__(256, 1)
sage_gemm(const float* __restrict__ mean, const float* __restrict__ h,
          const float* __restrict__ Wl, const float* __restrict__ Wr,
          const float* __restrict__ bias, float* __restrict__ out,
          int n, int relu) {
    extern __shared__ float sm[];
    float* Wt = sm;                 // [256][128] : Wt[k][j]
    float* As = sm + 256 * 128;     // [256][64]  : As[k][r]

    int tid = threadIdx.x;
    int row0 = blockIdx.x * 64;

    // Wt[k][j] = (k<128 ? Wl[j][k] : Wr[j][k-128])
    #pragma unroll
    for (int i = 0; i < 32; i++) {
        int fidx = i * 256 + tid;          // 0..8191
        int j  = fidx % 128;
        int k  = (fidx / 128) * 4;
        float4 v;
        if (k < 128) v = __ldg((const float4*)(Wl + j * DD + k));
        else         v = __ldg((const float4*)(Wr + j * DD + (k - 128)));
        Wt[(k + 0) * 128 + j] = v.x;
        Wt[(k + 1) * 128 + j] = v.y;
        Wt[(k + 2) * 128 + j] = v.z;
        Wt[(k + 3) * 128 + j] = v.w;
    }

    // A tile transposed: As[k][r]
    #pragma unroll
    for (int i = 0; i < 16; i++) {
        int fidx = i * 256 + tid;          // 0..4095
        int r  = fidx % 64;
        int k  = (fidx / 64) * 4;
        int row = row0 + r;
        float4 v = make_float4(0.f, 0.f, 0.f, 0.f);
        if (row < n) {
            if (k < 128) v = __ldg((const float4*)(mean + (long long)row * DD + k));
            else         v = __ldg((const float4*)(h    + (long long)row * DD + (k - 128)));
        }
        As[(k + 0) * 64 + r] = v.x;
        As[(k + 1) * 64 + r] = v.y;
        As[(k + 2) * 64 + r] = v.z;
        As[(k + 3) * 64 + r] = v.w;
    }
    __syncthreads();

    int tx = tid & 31;        // column group: cols tx*4 .. tx*4+3
    int ty = tid >> 5;        // row group:    rows ty*8 .. ty*8+7 (ty == warp id)
    int col = tx * 4;

    u64 acc2[4][4];           // [row-pair p: rows 2p,2p+1][col c]
    #pragma unroll
    for (int p = 0; p < 4; p++)
        #pragma unroll
        for (int c = 0; c < 4; c++) acc2[p][c] = 0ull;

    #pragma unroll 4
    for (int k = 0; k < 256; k++) {
        float4 w = *(const float4*)(Wt + k * 128 + col);
        u64 wp0 = dup2(w.x), wp1 = dup2(w.y), wp2 = dup2(w.z), wp3 = dup2(w.w);
        ulonglong2 q0 = *(const ulonglong2*)(As + k * 64 + ty * 8);       // rows 0-3
        ulonglong2 q1 = *(const ulonglong2*)(As + k * 64 + ty * 8 + 4);   // rows 4-7
        u64 pr[4] = {q0.x, q0.y, q1.x, q1.y};
        #pragma unroll
        for (int p = 0; p < 4; p++) {
            fma2(acc2[p][0], pr[p], wp0);
            fma2(acc2[p][1], pr[p], wp1);
            fma2(acc2[p][2], pr[p], wp2);
            fma2(acc2[p][3], pr[p], wp3);
        }
    }

    float4 bv = __ldg((const float4*)(bias + col));
    #pragma unroll
    for (int p = 0; p < 4; p++) {
        float lo[4], hi[4];
        #pragma unroll
        for (int c = 0; c < 4; c++) unpk(lo[c], hi[c], acc2[p][c]);
        int row = row0 + ty * 8 + 2 * p;
        if (row < n) {
            float4 o = make_float4(lo[0] + bv.x, lo[1] + bv.y, lo[2] + bv.z, lo[3] + bv.w);
            if (relu) { o.x = fmaxf(o.x, 0.f); o.y = fmaxf(o.y, 0.f);
                        o.z = fmaxf(o.z, 0.f); o.w = fmaxf(o.w, 0.f); }
            *(float4*)(out + (long long)row * DD + col) = o;
        }
        if (row + 1 < n) {
            float4 o = make_float4(hi[0] + bv.x, hi[1] + bv.y, hi[2] + bv.z, hi[3] + bv.w);
            if (relu) { o.x = fmaxf(o.x, 0.f); o.y = fmaxf(o.y, 0.f);
                        o.z = fmaxf(o.z, 0.f); o.w = fmaxf(o.w, 0.f); }
            *(float4*)(out + (long long)(row + 1) * DD + col) = o;
        }
    }
}

// ==================== launch ====================
extern "C" void kernel_launch(void* const* d_in, const int* in_sizes, int n_in,
                              void* d_out, int out_size) {
    const float* x   = (const float*)d_in[0];
    const int*   ei  = (const int*)d_in[1];     // int32
    const float* W1l = (const float*)d_in[2];
    const float* W1r = (const float*)d_in[3];
    const float* W2l = (const float*)d_in[4];
    const float* W2r = (const float*)d_in[5];
    const float* W3l = (const float*)d_in[6];
    const float* W3r = (const float*)d_in[7];
    const float* b1  = (const float*)d_in[8];
    const float* b2  = (const float*)d_in[9];
    const float* b3  = (const float*)d_in[10];
    float* out = (float*)d_out;

    int n = in_sizes[0] / DD;
    long long E = (long long)in_sizes[1] / 2;

    float *agg, *h0, *h1;
    int *cnt, *cur, *incl, *bsum, *rowptr, *csr;
    cudaGetSymbolAddress((void**)&agg,    g_agg);
    cudaGetSymbolAddress((void**)&h0,     g_h0);
    cudaGetSymbolAddress((void**)&h1,     g_h1);
    cudaGetSymbolAddress((void**)&cnt,    g_cnt);
    cudaGetSymbolAddress((void**)&cur,    g_cur);
    cudaGetSymbolAddress((void**)&incl,   g_incl);
    cudaGetSymbolAddress((void**)&bsum,   g_bsum);
    cudaGetSymbolAddress((void**)&rowptr, g_rowptr);
    cudaGetSymbolAddress((void**)&csr,    g_csr);

    cudaFuncSetAttribute(sage_gemm, cudaFuncAttributeMaxDynamicSharedMemorySize,
                         (int)GEMM_SMEM);

    // ---- build CSR (dst-grouped), reused by all 3 layers ----
    cudaMemsetAsync(cnt, 0, (size_t)n * sizeof(int));
    cudaMemsetAsync(cur, 0, (size_t)n * sizeof(int));
    unsigned eblocks = (unsigned)((E + 255) / 256);
    deg_kernel<<<eblocks, 256>>>(ei + E, cnt, E);
    int nb = (n + SB - 1) / SB;
    scan1<<<nb, SB>>>(cnt, incl, bsum, n);
    scan2<<<1, 512>>>(bsum, nb);
    scan3<<<(n + 255) / 256, 256>>>(incl, cnt, bsum, rowptr, n, (int)E);
    place_kernel<<<eblocks, 256>>>(ei, rowptr, cur, csr, E);

    int agg_blocks  = (n + 7) / 8;          // 8 warps per block, warp per node
    int gemm_blocks = (n + 63) / 64;

    // Layer 1
    agg_kernel<<<agg_blocks, 256>>>(x, rowptr, csr, agg, n);
    sage_gemm<<<gemm_blocks, 256, GEMM_SMEM>>>(agg, x, W1l, W1r, b1, h0, n, 1);
    // Layer 2
    agg_kernel<<<agg_blocks, 256>>>(h0, rowptr, csr, agg, n);
    sage_gemm<<<gemm_blocks, 256, GEMM_SMEM>>>(agg, h0, W2l, W2r, b2, h1, n, 1);
    // Layer 3
    agg_kernel<<<agg_blocks, 256>>>(h1, rowptr, csr, agg, n);
    sage_gemm<<<gemm_blocks, 256, GEMM_SMEM>>>(agg, h1, W3l, W3r, b3, out, n, 0);
}

// round 5
// speedup vs baseline: 1.9839x; 1.0342x over previous
#include <cuda_runtime.h>
#include <cuda_fp16.h>
#include <stdint.h>

#define DD 128
#define NMAX 100000
#define EMAX 3200000
typedef unsigned long long u64;

// -------- device-global scratch (no runtime allocation allowed) --------
__device__ float  g_agg[(size_t)NMAX * DD];
__device__ float  g_h0 [(size_t)NMAX * DD];
__device__ float  g_h1 [(size_t)NMAX * DD];
__device__ __half g_h16[(size_t)NMAX * DD];   // fp16 mirror of current layer input
__device__ int    g_cnt [NMAX];
__device__ int    g_cur [NMAX];
__device__ int    g_incl[NMAX];
__device__ int    g_bsum[512];
__device__ int    g_rowptr[NMAX + 1];
__device__ int    g_csr [EMAX];

// ==================== CSR build ====================
__global__ void deg_kernel(const int* __restrict__ dst, int* __restrict__ cnt, long long E) {
    long long e = (long long)blockIdx.x * blockDim.x + threadIdx.x;
    if (e < E) atomicAdd(&cnt[dst[e]], 1);
}

#define SB 256
__global__ void scan1(const int* __restrict__ cnt, int* __restrict__ incl,
                      int* __restrict__ bsum, int n) {
    __shared__ int sm[SB];
    int i = blockIdx.x * SB + threadIdx.x;
    int v = (i < n) ? cnt[i] : 0;
    sm[threadIdx.x] = v;
    __syncthreads();
    for (int off = 1; off < SB; off <<= 1) {
        int t = (threadIdx.x >= off) ? sm[threadIdx.x - off] : 0;
        __syncthreads();
        sm[threadIdx.x] += t;
        __syncthreads();
    }
    if (i < n) incl[i] = sm[threadIdx.x];
    if (threadIdx.x == SB - 1) bsum[blockIdx.x] = sm[SB - 1];
}

__global__ void scan2(int* __restrict__ bsum, int nb) {  // exclusive scan, nb <= 512
    __shared__ int sm[512];
    int v = (threadIdx.x < nb) ? bsum[threadIdx.x] : 0;
    sm[threadIdx.x] = v;
    __syncthreads();
    for (int off = 1; off < 512; off <<= 1) {
        int t = (threadIdx.x >= off) ? sm[threadIdx.x - off] : 0;
        __syncthreads();
        sm[threadIdx.x] += t;
        __syncthreads();
    }
    if (threadIdx.x < nb) bsum[threadIdx.x] = sm[threadIdx.x] - v;
}

__global__ void scan3(const int* __restrict__ incl, const int* __restrict__ cnt,
                      const int* __restrict__ bsum, int* __restrict__ rowptr,
                      int n, int E) {
    int i = blockIdx.x * 256 + threadIdx.x;
    if (i < n) rowptr[i] = incl[i] - cnt[i] + bsum[i / SB];
    if (i == 0) rowptr[n] = E;
}

__global__ void place_kernel(const int* __restrict__ ei, const int* __restrict__ rowptr,
                             int* __restrict__ cur, int* __restrict__ csr, long long E) {
    long long e = (long long)blockIdx.x * blockDim.x + threadIdx.x;
    if (e < E) {
        int s = ei[e];
        int d = ei[E + e];
        int pos = rowptr[d] + atomicAdd(&cur[d], 1);
        csr[pos] = s;
    }
}

// ==================== fp32 -> fp16 conversion (for layer-1 input) ====================
__global__ void conv16_kernel(const float* __restrict__ src, __half* __restrict__ dst, int total4) {
    int i = blockIdx.x * blockDim.x + threadIdx.x;
    if (i < total4) {
        float4 v = __ldg((const float4*)src + i);
        __half2 a = __floats2half2_rn(v.x, v.y);
        __half2 b = __floats2half2_rn(v.z, v.w);
        *((uint2*)dst + i) = make_uint2(*(uint32_t*)&a, *(uint32_t*)&b);
    }
}

// ==================== mean aggregation (warp per dst node, fp16 gather) ====================
__global__ void agg_kernel(const __half* __restrict__ h16, const int* __restrict__ rowptr,
                           const int* __restrict__ csr, float* __restrict__ agg, int n) {
    int d = blockIdx.x * (blockDim.x >> 5) + (threadIdx.x >> 5);
    int lane = threadIdx.x & 31;
    if (d >= n) return;
    int beg = __ldg(&rowptr[d]);
    int end = __ldg(&rowptr[d + 1]);
    float4 acc = make_float4(0.f, 0.f, 0.f, 0.f);
    for (int j = beg; j < end; j += 32) {
        int cnt = min(32, end - j);
        int s = (lane < cnt) ? __ldg(&csr[j + lane]) : 0;
        #pragma unroll 4
        for (int t = 0; t < cnt; t++) {
            int ss = __shfl_sync(0xffffffffu, s, t);
            // lane covers feature dims [4*lane .. 4*lane+3] (8 bytes)
            uint2 raw = __ldg((const uint2*)(h16 + (size_t)ss * DD) + lane);
            __half2 a = *(__half2*)&raw.x;
            __half2 b = *(__half2*)&raw.y;
            float2 fa = __half22float2(a);
            float2 fb = __half22float2(b);
            acc.x += fa.x; acc.y += fa.y; acc.z += fb.x; acc.w += fb.y;
        }
    }
    float inv = 1.0f / fmaxf((float)(end - beg), 1.0f);
    acc.x *= inv; acc.y *= inv; acc.z *= inv; acc.w *= inv;
    *((float4*)(agg + (size_t)d * DD) + lane) = acc;
}

// ==================== fused SAGE GEMM (f32x2 packed FFMA) ====================
// out[n,:] = mean[n,:] @ Wl^T + h[n,:] @ Wr^T + b   (+ optional ReLU)
// C = A @ Wt, A = [mean | h] (N x 256), Wt = [Wl^T ; Wr^T] (256 x 128).
// Also emits fp16 copy of the output (next layer's gather operand) when h16out != null.
#define GEMM_SMEM ((256 * 128 + 256 * 64) * sizeof(float))

__device__ __forceinline__ void fma2(u64& d, u64 a, u64 b) {
    asm("fma.rn.f32x2 %0, %1, %2, %0;" : "+l"(d) : "l"(a), "l"(b));
}
__device__ __forceinline__ u64 dup2(float x) {
    u64 r;
    asm("mov.b64 %0, {%1, %1};" : "=l"(r) : "r"(__float_as_uint(x)));
    return r;
}
__device__ __forceinline__ void unpk(float& lo, float& hi, u64 v) {
    unsigned a, b;
    asm("mov.b64 {%0, %1}, %2;" : "=r"(a), "=r"(b) : "l"(v));
    lo = __uint_as_float(a); hi = __uint_as_float(b);
}

__global__ void __launch_bounds__(256, 1)
sage_gemm(const float* __restrict__ mean, const float* __restrict__ h,
          const float* __restrict__ Wl, const float* __restrict__ Wr,
          const float* __restrict__ bias, float* __restrict__ out,
          __half* __restrict__ h16out, int n, int relu) {
    extern __shared__ float sm[];
    float* Wt = sm;                 // [256][128] : Wt[k][j]
    float* As = sm + 256 * 128;     // [256][64]  : As[k][r]

    int tid = threadIdx.x;
    int row0 = blockIdx.x * 64;

    // Wt[k][j] = (k<128 ? Wl[j][k] : Wr[j][k-128])
    #pragma unroll
    for (int i = 0; i < 32; i++) {
        int fidx = i * 256 + tid;          // 0..8191
        int j  = fidx % 128;
        int k  = (fidx / 128) * 4;
        float4 v;
        if (k < 128) v = __ldg((const float4*)(Wl + j * DD + k));
        else         v = __ldg((const float4*)(Wr + j * DD + (k - 128)));
        Wt[(k + 0) * 128 + j] = v.x;
        Wt[(k + 1) * 128 + j] = v.y;
        Wt[(k + 2) * 128 + j] = v.z;
        Wt[(k + 3) * 128 + j] = v.w;
    }

    // A tile transposed: As[k][r]
    #pragma unroll
    for (int i = 0; i < 16; i++) {
        int fidx = i * 256 + tid;          // 0..4095
        int r  = fidx % 64;
        int k  = (fidx / 64) * 4;
        int row = row0 + r;
        float4 v = make_float4(0.f, 0.f, 0.f, 0.f);
        if (row < n) {
            if (k < 128) v = __ldg((const float4*)(mean + (size_t)row * DD + k));
            else         v = __ldg((const float4*)(h    + (size_t)row * DD + (k - 128)));
        }
        As[(k + 0) * 64 + r] = v.x;
        As[(k + 1) * 64 + r] = v.y;
        As[(k + 2) * 64 + r] = v.z;
        As[(k + 3) * 64 + r] = v.w;
    }
    __syncthreads();

    int tx = tid & 31;        // column group: cols tx*4 .. tx*4+3
    int ty = tid >> 5;        // row group:    rows ty*8 .. ty*8+7 (ty == warp id)
    int col = tx * 4;

    u64 acc2[4][4];           // [row-pair p: rows 2p,2p+1][col c]
    #pragma unroll
    for (int p = 0; p < 4; p++)
        #pragma unroll
        for (int c = 0; c < 4; c++) acc2[p][c] = 0ull;

    #pragma unroll 4
    for (int k = 0; k < 256; k++) {
        float4 w = *(const float4*)(Wt + k * 128 + col);
        u64 wp0 = dup2(w.x), wp1 = dup2(w.y), wp2 = dup2(w.z), wp3 = dup2(w.w);
        ulonglong2 q0 = *(const ulonglong2*)(As + k * 64 + ty * 8);       // rows 0-3
        ulonglong2 q1 = *(const ulonglong2*)(As + k * 64 + ty * 8 + 4);   // rows 4-7
        u64 pr[4] = {q0.x, q0.y, q1.x, q1.y};
        #pragma unroll
        for (int p = 0; p < 4; p++) {
            fma2(acc2[p][0], pr[p], wp0);
            fma2(acc2[p][1], pr[p], wp1);
            fma2(acc2[p][2], pr[p], wp2);
            fma2(acc2[p][3], pr[p], wp3);
        }
    }

    float4 bv = __ldg((const float4*)(bias + col));
    #pragma unroll
    for (int p = 0; p < 4; p++) {
        float lo[4], hi[4];
        #pragma unroll
        for (int c = 0; c < 4; c++) unpk(lo[c], hi[c], acc2[p][c]);
        int row = row0 + ty * 8 + 2 * p;
        if (row < n) {
            float4 o = make_float4(lo[0] + bv.x, lo[1] + bv.y, lo[2] + bv.z, lo[3] + bv.w);
            if (relu) { o.x = fmaxf(o.x, 0.f); o.y = fmaxf(o.y, 0.f);
                        o.z = fmaxf(o.z, 0.f); o.w = fmaxf(o.w, 0.f); }
            *(float4*)(out + (size_t)row * DD + col) = o;
            if (h16out) {
                __half2 a = __floats2half2_rn(o.x, o.y);
                __half2 b = __floats2half2_rn(o.z, o.w);
                *(uint2*)(h16out + (size_t)row * DD + col) =
                    make_uint2(*(uint32_t*)&a, *(uint32_t*)&b);
            }
        }
        if (row + 1 < n) {
            float4 o = make_float4(hi[0] + bv.x, hi[1] + bv.y, hi[2] + bv.z, hi[3] + bv.w);
            if (relu) { o.x = fmaxf(o.x, 0.f); o.y = fmaxf(o.y, 0.f);
                        o.z = fmaxf(o.z, 0.f); o.w = fmaxf(o.w, 0.f); }
            *(float4*)(out + (size_t)(row + 1) * DD + col) = o;
            if (h16out) {
                __half2 a = __floats2half2_rn(o.x, o.y);
                __half2 b = __floats2half2_rn(o.z, o.w);
                *(uint2*)(h16out + (size_t)(row + 1) * DD + col) =
                    make_uint2(*(uint32_t*)&a, *(uint32_t*)&b);
            }
        }
    }
}

// ==================== launch ====================
extern "C" void kernel_launch(void* const* d_in, const int* in_sizes, int n_in,
                              void* d_out, int out_size) {
    const float* x   = (const float*)d_in[0];
    const int*   ei  = (const int*)d_in[1];     // int32
    const float* W1l = (const float*)d_in[2];
    const float* W1r = (const float*)d_in[3];
    const float* W2l = (const float*)d_in[4];
    const float* W2r = (const float*)d_in[5];
    const float* W3l = (const float*)d_in[6];
    const float* W3r = (const float*)d_in[7];
    const float* b1  = (const float*)d_in[8];
    const float* b2  = (const float*)d_in[9];
    const float* b3  = (const float*)d_in[10];
    float* out = (float*)d_out;

    int n = in_sizes[0] / DD;
    long long E = (long long)in_sizes[1] / 2;

    float *agg, *h0, *h1;
    __half* h16;
    int *cnt, *cur, *incl, *bsum, *rowptr, *csr;
    cudaGetSymbolAddress((void**)&agg,    g_agg);
    cudaGetSymbolAddress((void**)&h0,     g_h0);
    cudaGetSymbolAddress((void**)&h1,     g_h1);
    cudaGetSymbolAddress((void**)&h16,    g_h16);
    cudaGetSymbolAddress((void**)&cnt,    g_cnt);
    cudaGetSymbolAddress((void**)&cur,    g_cur);
    cudaGetSymbolAddress((void**)&incl,   g_incl);
    cudaGetSymbolAddress((void**)&bsum,   g_bsum);
    cudaGetSymbolAddress((void**)&rowptr, g_rowptr);
    cudaGetSymbolAddress((void**)&csr,    g_csr);

    cudaFuncSetAttribute(sage_gemm, cudaFuncAttributeMaxDynamicSharedMemorySize,
                         (int)GEMM_SMEM);

    // ---- build CSR (dst-grouped), reused by all 3 layers ----
    cudaMemsetAsync(cnt, 0, (size_t)n * sizeof(int));
    cudaMemsetAsync(cur, 0, (size_t)n * sizeof(int));
    unsigned eblocks = (unsigned)((E + 255) / 256);
    deg_kernel<<<eblocks, 256>>>(ei + E, cnt, E);
    int nb = (n + SB - 1) / SB;
    scan1<<<nb, SB>>>(cnt, incl, bsum, n);
    scan2<<<1, 512>>>(bsum, nb);
    scan3<<<(n + 255) / 256, 256>>>(incl, cnt, bsum, rowptr, n, (int)E);
    place_kernel<<<eblocks, 256>>>(ei, rowptr, cur, csr, E);

    // fp16 mirror of x (layer-1 gather operand)
    int total4 = n * DD / 4;
    conv16_kernel<<<(total4 + 255) / 256, 256>>>(x, h16, total4);

    int agg_blocks  = (n + 7) / 8;          // 8 warps per block, warp per node
    int gemm_blocks = (n + 63) / 64;

    // Layer 1
    agg_kernel<<<agg_blocks, 256>>>(h16, rowptr, csr, agg, n);
    sage_gemm<<<gemm_blocks, 256, GEMM_SMEM>>>(agg, x, W1l, W1r, b1, h0, h16, n, 1);
    // Layer 2
    agg_kernel<<<agg_blocks, 256>>>(h16, rowptr, csr, agg, n);
    sage_gemm<<<gemm_blocks, 256, GEMM_SMEM>>>(agg, h0, W2l, W2r, b2, h1, h16, n, 1);
    // Layer 3
    agg_kernel<<<agg_blocks, 256>>>(h16, rowptr, csr, agg, n);
    sage_gemm<<<gemm_blocks, 256, GEMM_SMEM>>>(agg, h1, W3l, W3r, b3, out, (/*no mirror*/ (__half*)0), n, 0);
}